// round 16
// baseline (speedup 1.0000x reference)
#include <cuda_runtime.h>
#include <cuda_fp16.h>
#include <math.h>
#include <stdint.h>

#define BATCH 2
#define SEQ   2048
#define MTOT  (BATCH*SEQ)      // 4096
#define DE    1024
#define NH    16
#define DK    64
#define VOCAB 32000
#define NL    4
#define QS    (4*DE)           // fused qkvg row stride
#define PI_F  3.14159265358979323846f
#define TABSTRIDE 132          // float4 entries per (l,h)

#define BM 128
#define BN 128
#define BK 64
#define SPAD 72                     // fp16 elems per smem row (144B, conflict-free)
#define PLANE_BYTES (128*SPAD*2)    // 18432
#define STAGE_BYTES (2*PLANE_BYTES) // 36864 (A, B)
#define NSTAGE 4
#define SMEM_GEMM (NSTAGE*STAGE_BYTES) // 147456 -> 1 CTA/SM, regs unbounded

// ---------------- scratch (static device globals; no allocation) ----------------
__device__ float d_rnorm[VOCAB];
__device__ float d_x   [MTOT*DE];
__device__ __half d_qkvg[(size_t)MTOT*QS];
__device__ __half d_xh [MTOT*DE];
__device__ __half d_hhh[MTOT*DE];
__device__ __half d_eh [(size_t)VOCAB*DE];
__device__ __half d_wh [(size_t)5*NL*DE*DE];   // [l][Wq,Wk,Wv,Wg], then [l][Wo]
__device__ float4 d_tab[NL*NH*TABSTRIDE];      // (mask, cosD, sinD, 0) per (l,h,-rel)

__device__ __forceinline__ float wredsum(float x) {
#pragma unroll
    for (int o = 16; o > 0; o >>= 1) x += __shfl_xor_sync(0xFFFFFFFFu, x, o);
    return x;
}
__device__ __forceinline__ unsigned smem_u32(const void* p) {
    return (unsigned)__cvta_generic_to_shared(p);
}
__device__ __forceinline__ float ftanh(float x) {
    float y;
    asm("tanh.approx.f32 %0, %1;" : "=f"(y) : "f"(x));
    return y;
}

#define CP16(dst_u32, src_ptr) \
    asm volatile("cp.async.cg.shared.global [%0], [%1], 16;" :: "r"(dst_u32), "l"(src_ptr))
#define CP_COMMIT() asm volatile("cp.async.commit_group;" ::: "memory")
#define CP_WAIT(N)  asm volatile("cp.async.wait_group %0;" :: "n"(N) : "memory")

// ---------------- fused: embed row norm + fp16 conversion (MLP=4 per thread) ----------
__global__ void rnormconv_kernel(const float* __restrict__ embed, float* __restrict__ rnorm,
                                 __half* __restrict__ eh) {
    int v = blockIdx.x;
    int tid = threadIdx.x;                 // 64 threads
    const float4* row = (const float4*)(embed + (size_t)v * DE);   // 256 float4
    float4 f0 = row[tid];
    float4 f1 = row[tid + 64];
    float4 f2 = row[tid + 128];
    float4 f3 = row[tid + 192];
    float s = f0.x*f0.x + f0.y*f0.y + f0.z*f0.z + f0.w*f0.w
            + f1.x*f1.x + f1.y*f1.y + f1.z*f1.z + f1.w*f1.w
            + f2.x*f2.x + f2.y*f2.y + f2.z*f2.z + f2.w*f2.w
            + f3.x*f3.x + f3.y*f3.y + f3.z*f3.z + f3.w*f3.w;
    s = wredsum(s);
    __shared__ float sh2[2];
    if ((tid & 31) == 0) sh2[tid >> 5] = s;
    __syncthreads();
    if (tid == 0) rnorm[v] = 1.0f / fmaxf(sqrtf(sh2[0] + sh2[1]), 1e-12f);
    __half2* H = (__half2*)(eh + (size_t)v * DE);
    H[2*tid]           = __floats2half2_rn(f0.x, f0.y);
    H[2*tid+1]         = __floats2half2_rn(f0.z, f0.w);
    H[2*(tid+64)]      = __floats2half2_rn(f1.x, f1.y);
    H[2*(tid+64)+1]    = __floats2half2_rn(f1.z, f1.w);
    H[2*(tid+128)]     = __floats2half2_rn(f2.x, f2.y);
    H[2*(tid+128)+1]   = __floats2half2_rn(f2.z, f2.w);
    H[2*(tid+192)]     = __floats2half2_rn(f3.x, f3.y);
    H[2*(tid+192)+1]   = __floats2half2_rn(f3.z, f3.w);
}

// ---------------- embedding lookup: writes x fp32 and xh fp16 ----------------
__global__ void embed_kernel(const int* __restrict__ ids, const float* __restrict__ embed,
                             const float* __restrict__ rnorm, const float* __restrict__ sE,
                             float* __restrict__ x, __half* __restrict__ xh) {
    int m = blockIdx.x;
    int id = ids[m];
    float sc = rnorm[id] * expf(*sE);
    const float4* row = (const float4*)(embed + (size_t)id * DE);
    int i = threadIdx.x;
    float4 r = row[i];
    r.x *= sc; r.y *= sc; r.z *= sc; r.w *= sc;
    ((float4*)(x + (size_t)m * DE))[i] = r;
    __half2* hp = (__half2*)(xh + (size_t)m * DE);
    hp[2*i]   = __floats2half2_rn(r.x, r.y);
    hp[2*i+1] = __floats2half2_rn(r.z, r.w);
}

// ---------------- ALL weights fp32 -> fp16, one launch, 4 float4/thread ----------------
__global__ void convall_kernel(const float* __restrict__ Wq, const float* __restrict__ Wk,
                               const float* __restrict__ Wv, const float* __restrict__ Wg,
                               const float* __restrict__ Wo, __half* __restrict__ wh) {
    const size_t LW  = (size_t)DE * DE;
    const size_t QPM = LW / 4;
    size_t qbase = ((size_t)blockIdx.x * blockDim.x + threadIdx.x) * 4;
    float4 v[4];
    __half2* Hd[4];
    size_t offs[4];
#pragma unroll
    for (int u = 0; u < 4; u++) {
        size_t q = qbase + u;
        int mat = (int)(q / QPM);
        size_t off = q % QPM;
        const float* src;
        size_t dst;
        if (mat < 16) {
            int l = mat >> 2, f = mat & 3;
            src = (f == 0 ? Wq : f == 1 ? Wk : f == 2 ? Wv : Wg) + (size_t)l * LW;
            dst = (size_t)l * 4 * LW + (size_t)f * LW;
        } else {
            int l = mat - 16;
            src = Wo + (size_t)l * LW;
            dst = (size_t)NL * 4 * LW + (size_t)l * LW;
        }
        v[u] = ((const float4*)src)[off];
        Hd[u] = (__half2*)(wh + dst);
        offs[u] = off;
    }
#pragma unroll
    for (int u = 0; u < 4; u++) {
        Hd[u][2*offs[u]]   = __floats2half2_rn(v[u].x, v[u].y);
        Hd[u][2*offs[u]+1] = __floats2half2_rn(v[u].z, v[u].w);
    }
}

// ---------------- per-(l,h,rel) mask/rotation table (precise trig, one launch) --------
__global__ void tab_kernel(const float* __restrict__ sw_all, float4* __restrict__ tab) {
    int l = blockIdx.x >> 4;
    int h = blockIdx.x & 15;
    int j = threadIdx.x;                 // j = -rel
    if (j >= 129) return;
    float w = expf(sw_all[l*NH + h]) + 1.0f;
    float phi = (w < 128.0f) ? 0.5f * (cosf(PI_F * w / 128.0f) + 1.0f) : 0.0f;
    float phiw = phi / w;
    float rel = -(float)j;
    float mask = 0.5f * (cosf(PI_F * rel / w) + 1.0f);
    float D = rel * phiw;
    tab[(size_t)(l*NH + h) * TABSTRIDE + j] = make_float4(mask, cosf(D), sinf(D), 0.0f);
}

// ---------------- fp16 tensor-core NT GEMM, cp.async 4-stage (dist 3), BK=64 ----------
#define MMA_F16(C, A, B)                                                       \
    asm volatile(                                                              \
        "mma.sync.aligned.m16n8k16.row.col.f32.f16.f16.f32 "                   \
        "{%0,%1,%2,%3}, {%4,%5,%6,%7}, {%8,%9}, {%0,%1,%2,%3};\n"              \
        : "+f"((C)[0]), "+f"((C)[1]), "+f"((C)[2]), "+f"((C)[3])               \
        : "r"((A)[0]), "r"((A)[1]), "r"((A)[2]), "r"((A)[3]),                  \
          "r"((B)[0]), "r"((B)[1]))

__global__ __launch_bounds__(256) void gemm_f16(
    const __half* __restrict__ A, const __half* __restrict__ B,
    float* __restrict__ C, int M, int N, int K,
    const float* __restrict__ colScale, const float* __restrict__ scalarLog,
    int accumulate, __half* __restrict__ Chalf, int normKV)
{
    extern __shared__ __align__(128) char smem[];
    uint32_t sbase = smem_u32(smem);

    int tid  = threadIdx.x;
    int lane = tid & 31;
    int warp = tid >> 5;
    int wm = (warp >> 2) * 64;
    int wn = (warp & 3) * 32;
    int bm = blockIdx.y * BM;
    int bn = blockIdx.x * BN;

    int r0  = tid >> 3;            // 0..31
    int c16 = tid & 7;             // 0..7
    const char* gA0 = (const char*)(A + (size_t)(bm + r0) * K + c16 * 8);
    const char* gB0 = (const char*)(B + (size_t)(bn + r0) * K + c16 * 8);
    uint32_t s0 = r0 * (SPAD*2) + c16 * 16;
    const size_t rowstep = (size_t)32 * K * 2;
    const uint32_t srowstep = 32 * (SPAD*2);

#define PREFETCH(st, k0)                                                       \
    {                                                                          \
        uint32_t sd = sbase + (st) * STAGE_BYTES;                              \
        size_t gk = (size_t)(k0) * 2;                                          \
        _Pragma("unroll")                                                      \
        for (int i = 0; i < 4; i++) {                                          \
            CP16(sd + 0*PLANE_BYTES + s0 + i*srowstep, gA0 + gk + i*rowstep);  \
            CP16(sd + 1*PLANE_BYTES + s0 + i*srowstep, gB0 + gk + i*rowstep);  \
        }                                                                      \
        CP_COMMIT();                                                           \
    }

    float c[4][4][4];
#pragma unroll
    for (int i = 0; i < 4; i++)
#pragma unroll
        for (int j = 0; j < 4; j++)
#pragma unroll
            for (int q = 0; q < 4; q++) c[i][j][q] = 0.f;

    int arow_l = lane & 15;
    int acol_l = (lane >> 4) << 3;
    int brow_l = (lane & 7) + ((lane >> 4) << 3);
    int bcol_l = ((lane >> 3) & 1) << 3;

    int niter = K / BK;                 // 16 for all our shapes
    PREFETCH(0, 0);
    PREFETCH(1, BK);
    PREFETCH(2, 2*BK);
    CP_WAIT(2);
    __syncthreads();

    for (int it = 0; it < niter; ++it) {
        int st = it & (NSTAGE - 1);
        if (it + 3 < niter) PREFETCH((it + 3) & (NSTAGE - 1), (it + 3) * BK);

        const __half* sA = (const __half*)(smem + st*STAGE_BYTES + 0*PLANE_BYTES);
        const __half* sB = (const __half*)(smem + st*STAGE_BYTES + 1*PLANE_BYTES);

#pragma unroll
        for (int ks = 0; ks < 4; ks++) {
            unsigned Af[4][4], Bf[4][2];
            int acol = ks * 16 + acol_l;
            int bcol = ks * 16 + bcol_l;
#pragma unroll
            for (int mt = 0; mt < 4; mt++) {
                unsigned sa = smem_u32(&sA[(wm + mt*16 + arow_l) * SPAD + acol]);
                asm volatile("ldmatrix.sync.aligned.m8n8.x4.shared.b16 {%0,%1,%2,%3}, [%4];\n"
                    : "=r"(Af[mt][0]), "=r"(Af[mt][1]), "=r"(Af[mt][2]), "=r"(Af[mt][3]) : "r"(sa));
            }
#pragma unroll
            for (int p = 0; p < 2; p++) {
                unsigned sb = smem_u32(&sB[(wn + p*16 + brow_l) * SPAD + bcol]);
                unsigned q0, q1, q2, q3;
                asm volatile("ldmatrix.sync.aligned.m8n8.x4.shared.b16 {%0,%1,%2,%3}, [%4];\n"
                    : "=r"(q0), "=r"(q1), "=r"(q2), "=r"(q3) : "r"(sb));
                Bf[p*2][0] = q0; Bf[p*2][1] = q1; Bf[p*2+1][0] = q2; Bf[p*2+1][1] = q3;
            }
#pragma unroll
            for (int mt = 0; mt < 4; mt++)
#pragma unroll
                for (int nt = 0; nt < 4; nt++)
                    MMA_F16(c[mt][nt], Af[mt], Bf[nt]);
        }

        if (it + 1 < niter) {
            if (it + 3 < niter)      { CP_WAIT(2); }
            else if (it + 2 < niter) { CP_WAIT(1); }
            else                     { CP_WAIT(0); }
            __syncthreads();
        }
    }

    int g  = lane >> 2;
    int t2 = (lane & 3) * 2;

    // ---- fused k/v head normalization (fused qkvg GEMM only) ----
    if (normKV && ((bn >> 10) == 1 || (bn >> 10) == 2)) {
        float* ssum = (float*)smem;          // 128 rows x 4 col-groups
        __syncthreads();                     // mainloop smem reads done
#pragma unroll
        for (int mt = 0; mt < 4; mt++) {
#pragma unroll
            for (int rh = 0; rh < 2; rh++) {
                float p = 0.f;
#pragma unroll
                for (int nt = 0; nt < 4; nt++) {
                    float a = c[mt][nt][rh*2], b = c[mt][nt][rh*2+1];
                    p = fmaf(a, a, p); p = fmaf(b, b, p);
                }
                p += __shfl_xor_sync(0xFFFFFFFFu, p, 1);
                p += __shfl_xor_sync(0xFFFFFFFFu, p, 2);
                if ((lane & 3) == 0)
                    ssum[(wm + mt*16 + g + rh*8) * 4 + (wn >> 5)] = p;
            }
        }
        __syncthreads();
        int basegrp = (wn >> 5) & ~1;
#pragma unroll
        for (int mt = 0; mt < 4; mt++) {
#pragma unroll
            for (int rh = 0; rh < 2; rh++) {
                int rl = wm + mt*16 + g + rh*8;
                float hs = ssum[rl*4 + basegrp] + ssum[rl*4 + basegrp + 1];
                float ik = 1.0f / fmaxf(sqrtf(hs), 1e-12f);
#pragma unroll
                for (int nt = 0; nt < 4; nt++) {
                    c[mt][nt][rh*2]   *= ik;
                    c[mt][nt][rh*2+1] *= ik;
                }
            }
        }
    }

    // epilogue
    float sc = scalarLog ? __expf(*scalarLog) : 1.0f;
#pragma unroll
    for (int mt = 0; mt < 4; mt++) {
#pragma unroll
        for (int nt = 0; nt < 4; nt++) {
            int row = bm + wm + mt*16 + g;
            int col = bn + wn + nt*8 + t2;
            float cs0 = colScale ? colScale[col]   : 1.0f;
            float cs1 = colScale ? colScale[col+1] : 1.0f;
            float v0 = c[mt][nt][0] * sc * cs0;
            float v1 = c[mt][nt][1] * sc * cs1;
            float v2 = c[mt][nt][2] * sc * cs0;
            float v3 = c[mt][nt][3] * sc * cs1;
            if (C) {
                float* p0 = C + (size_t)row * N + col;
                float* p1 = C + (size_t)(row + 8) * N + col;
                if (accumulate) {
                    v0 += p0[0]; v1 += p0[1];
                    v2 += p1[0]; v3 += p1[1];
                }
                float2 a; a.x = v0; a.y = v1; *(float2*)p0 = a;
                float2 b; b.x = v2; b.y = v3; *(float2*)p1 = b;
            }
            if (Chalf) {
                *(__half2*)(Chalf + (size_t)row * N + col)       = __floats2half2_rn(v0, v1);
                *(__half2*)(Chalf + (size_t)(row + 8) * N + col) = __floats2half2_rn(v2, v3);
            }
        }
    }
}

// ---------------- fused attention: 8 lanes per (m,h), 4 units/warp ----------------
__global__ void attn_kernel(const __half* __restrict__ qkvg,
                            const float4* __restrict__ tabl,
                            const float* __restrict__ sw, const float* __restrict__ sr,
                            const float* __restrict__ sO, __half* __restrict__ hhh) {
    int gwarp = (blockIdx.x * blockDim.x + threadIdx.x) >> 5;
    int lane = threadIdx.x & 31;
    int u = lane >> 3;                 // unit 0..3
    int e = lane & 7;                  // element block 0..7
    int gid = gwarp * 4 + u;           // (h, m) unit id
    int h = gid >> 12;
    int m = gid & (MTOT - 1);
    int t = m & (SEQ - 1);

    float w  = __expf(sw[h]) + 1.0f;
    float r  = __expf(sr[h]) + 1.0f;
    float es = __expf(sO[h]);
    const float4* th = tabl + h * TABSTRIDE;

    size_t qoff = (size_t)m * QS + h * DK + e * 8;
    uint4 qraw = *(const uint4*)(qkvg + qoff);
    float qv[8];
    {
        const __half2* qh = (const __half2*)&qraw;
#pragma unroll
        for (int k2 = 0; k2 < 4; k2++) {
            float2 f = __half22float2(qh[k2]);
            qv[2*k2] = f.x; qv[2*k2+1] = f.y;
        }
    }
    float sq = 0.f;
#pragma unroll
    for (int k2 = 0; k2 < 8; k2++) sq = fmaf(qv[k2], qv[k2], sq);
    sq += __shfl_xor_sync(0xFFFFFFFFu, sq, 1);
    sq += __shfl_xor_sync(0xFFFFFFFFu, sq, 2);
    sq += __shfl_xor_sync(0xFFFFFFFFu, sq, 4);
    float iq = 1.0f / fmaxf(sqrtf(sq), 1e-12f);
#pragma unroll
    for (int k2 = 0; k2 < 8; k2++) qv[k2] *= iq;

    int LB = (int)ceilf(w) - 1;
    int lb = (LB > t) ? t : LB;        // per-unit lookback
    int tb0 = t - u;                   // t of unit 0 (warp-uniform)
    int lbmin = (LB > tb0) ? tb0 : LB; // warp-uniform common lookback

    const __half* kbase = qkvg + (size_t)(m - lb) * QS + h * DK + e * 8 + DE;

    float acc[8];
#pragma unroll
    for (int k2 = 0; k2 < 8; k2++) acc[k2] = 0.f;

#pragma unroll 4
    for (int i = 0; i <= lbmin; ++i) {
        const __half* kp = kbase + (size_t)i * QS;
        uint4 kraw = *(const uint4*)kp;
        uint4 vraw = *(const uint4*)(kp + DE);
        float4 tb = th[lb - i];
        float kf[8];
        {
            const __half2* kh = (const __half2*)&kraw;
#pragma unroll
            for (int k2 = 0; k2 < 4; k2++) {
                float2 f = __half22float2(kh[k2]);
                kf[2*k2] = f.x; kf[2*k2+1] = f.y;
            }
        }
        float d = 0.f;
#pragma unroll
        for (int k2 = 0; k2 < 8; k2++) d = fmaf(qv[k2], kf[k2], d);
        if (e == 0) {
            float pr = fmaf(qv[0], kf[0], qv[1] * kf[1]);
            float cr = qv[0] * kf[1] - qv[1] * kf[0];
            d = fmaf(tb.y - 1.0f, pr, fmaf(tb.z, cr, d));
        }
        d += __shfl_xor_sync(0xFFFFFFFFu, d, 1);
        d += __shfl_xor_sync(0xFFFFFFFFu, d, 2);
        d += __shfl_xor_sync(0xFFFFFFFFu, d, 4);
        float tmp = fmaxf(fmaf(r, d - 1.0f, 1.0f), 0.0f);
        float rho = tmp * tmp * tb.x;
        const __half2* vh = (const __half2*)&vraw;
#pragma unroll
        for (int k2 = 0; k2 < 4; k2++) {
            float2 f = __half22float2(vh[k2]);
            acc[2*k2]   = fmaf(rho, f.x, acc[2*k2]);
            acc[2*k2+1] = fmaf(rho, f.y, acc[2*k2+1]);
        }
    }

    if (lbmin < LB) {
#pragma unroll
        for (int ex = 1; ex <= 3; ++ex) {
            int i = lbmin + ex;
            bool valid = (i <= lb);
            int io = valid ? i : 0;
            const __half* kp = kbase + (size_t)io * QS;
            uint4 kraw = *(const uint4*)kp;
            uint4 vraw = *(const uint4*)(kp + DE);
            float4 tb = th[valid ? (lb - i) : 0];
            float mk = valid ? tb.x : 0.0f;
            float kf[8];
            {
                const __half2* kh = (const __half2*)&kraw;
#pragma unroll
                for (int k2 = 0; k2 < 4; k2++) {
                    float2 f = __half22float2(kh[k2]);
                    kf[2*k2] = f.x; kf[2*k2+1] = f.y;
                }
            }
            float d = 0.f;
#pragma unroll
            for (int k2 = 0; k2 < 8; k2++) d = fmaf(qv[k2], kf[k2], d);
            if (e == 0) {
                float pr = fmaf(qv[0], kf[0], qv[1] * kf[1]);
                float cr = qv[0] * kf[1] - qv[1] * kf[0];
                d = fmaf(tb.y - 1.0f, pr, fmaf(tb.z, cr, d));
            }
            d += __shfl_xor_sync(0xFFFFFFFFu, d, 1);
            d += __shfl_xor_sync(0xFFFFFFFFu, d, 2);
            d += __shfl_xor_sync(0xFFFFFFFFu, d, 4);
            float tmp = fmaxf(fmaf(r, d - 1.0f, 1.0f), 0.0f);
            float rho = tmp * tmp * mk;
            const __half2* vh = (const __half2*)&vraw;
#pragma unroll
            for (int k2 = 0; k2 < 4; k2++) {
                float2 f = __half22float2(vh[k2]);
                acc[2*k2]   = fmaf(rho, f.x, acc[2*k2]);
                acc[2*k2+1] = fmaf(rho, f.y, acc[2*k2+1]);
            }
        }
    }

    float hn2 = 0.f;
#pragma unroll
    for (int k2 = 0; k2 < 8; k2++) hn2 = fmaf(acc[k2], acc[k2], hn2);
    hn2 += __shfl_xor_sync(0xFFFFFFFFu, hn2, 1);
    hn2 += __shfl_xor_sync(0xFFFFFFFFu, hn2, 2);
    hn2 += __shfl_xor_sync(0xFFFFFFFFu, hn2, 4);
    float hn = fmaxf(sqrtf(hn2), 1e-8f);
    float us = ftanh(hn) / hn;

    uint4 graw = *(const uint4*)(qkvg + qoff + 3*DE);
    uint4 oraw;
    __half2* oh = (__half2*)&oraw;
    const __half2* gh = (const __half2*)&graw;
#pragma unroll
    for (int k2 = 0; k2 < 4; k2++) {
        float2 gf = __half22float2(gh[k2]);
        float s0 = gf.x / (1.0f + __expf(-gf.x));
        float s1 = gf.y / (1.0f + __expf(-gf.y));
        float g0 = ftanh(s0), g1 = ftanh(s1);
        float o0 = acc[2*k2]   * us * g0 * es;
        float o1 = acc[2*k2+1] * us * g1 * es;
        oh[k2] = __floats2half2_rn(o0, o1);
    }
    *(uint4*)(hhh + (size_t)m * DE + h * DK + e * 8) = oraw;
}

// ---------------- launch ----------------
extern "C" void kernel_launch(void* const* d_in, const int* in_sizes, int n_in,
                              void* d_out, int out_size) {
    const int*   ids   = (const int*)d_in[0];
    const float* embed = (const float*)d_in[1];
    const float* sE    = (const float*)d_in[2];
    const float* sF    = (const float*)d_in[3];
    const float* Wq    = (const float*)d_in[4];
    const float* Wk    = (const float*)d_in[5];
    const float* Wv    = (const float*)d_in[6];
    const float* Wg    = (const float*)d_in[7];
    const float* Wo    = (const float*)d_in[8];
    const float* sw    = (const float*)d_in[9];
    const float* sr    = (const float*)d_in[10];
    const float* sO    = (const float*)d_in[11];
    float* out = (float*)d_out;

    cudaFuncSetAttribute(gemm_f16, cudaFuncAttributeMaxDynamicSharedMemorySize, SMEM_GEMM);

    float *x, *rn;
    cudaGetSymbolAddress((void**)&x,   d_x);
    cudaGetSymbolAddress((void**)&rn,  d_rnorm);
    float4* tab;
    cudaGetSymbolAddress((void**)&tab, d_tab);
    __half *qkvg, *xh, *hhh, *eh, *wh;
    cudaGetSymbolAddress((void**)&qkvg, d_qkvg);
    cudaGetSymbolAddress((void**)&xh,  d_xh);
    cudaGetSymbolAddress((void**)&hhh, d_hhh);
    cudaGetSymbolAddress((void**)&eh,  d_eh);
    cudaGetSymbolAddress((void**)&wh,  d_wh);

    const size_t LW = (size_t)DE * DE;
    const size_t WO_BASE = (size_t)NL * 4 * LW;

    rnormconv_kernel<<<VOCAB, 64>>>(embed, rn, eh);
    embed_kernel<<<MTOT, 256>>>(ids, embed, rn, sE, x, xh);
    convall_kernel<<<(int)(20 * LW / 4 / 1024), 256>>>(Wq, Wk, Wv, Wg, Wo, wh);
    tab_kernel<<<NL*NH, 160>>>(sw, tab);

    dim3 gfused(QS / BN, MTOT / BM);   // (32, 32)
    dim3 gwo(DE / BN, MTOT / BM);      // (8, 32)
    int units = MTOT * NH;             // 65536
    int nblk_attn = (units / 4 * 32) / 256;   // 2048 blocks

    for (int l = 0; l < NL; ++l) {
        size_t fb = (size_t)l * 4 * LW;
        const float* swl = sw + l * NH;
        const float* srl = sr + l * NH;
        const float* sOl = sO + l * NH;
        const float4* tabl = tab + (size_t)l * NH * TABSTRIDE;

        gemm_f16<<<gfused, 256, SMEM_GEMM>>>(xh, wh + fb, nullptr,
                                             MTOT, QS, DE, nullptr, nullptr, 0, qkvg, 1);
        attn_kernel<<<nblk_attn, 256>>>(qkvg, tabl, swl, srl, sOl, hhh);
        gemm_f16<<<gwo, 256, SMEM_GEMM>>>(hhh, wh + WO_BASE + l*LW, x,
                                          MTOT, DE, DE, nullptr, nullptr, 1, xh, 0);
    }

    dim3 gfin(VOCAB / BN, MTOT / BM);  // (250, 32)
    gemm_f16<<<gfin, 256, SMEM_GEMM>>>(xh, eh, out, MTOT, VOCAB, DE, rn, sF, 0, nullptr, 0);
}

// round 17
// speedup vs baseline: 1.2756x; 1.2756x over previous
#include <cuda_runtime.h>
#include <cuda_fp16.h>
#include <math.h>
#include <stdint.h>

#define BATCH 2
#define SEQ   2048
#define MTOT  (BATCH*SEQ)      // 4096
#define DE    1024
#define NH    16
#define DK    64
#define VOCAB 32000
#define NL    4
#define QS    (4*DE)           // fused qkvg row stride
#define PI_F  3.14159265358979323846f
#define TABSTRIDE 132          // float4 entries per (l,h)

#define BM 128
#define BN 128
#define BK 64
#define GK 1024                     // compile-time K for ALL gemms
#define SPAD 72                     // fp16 elems per smem row (144B, conflict-free)
#define PLANE_BYTES (128*SPAD*2)    // 18432
#define STAGE_BYTES (2*PLANE_BYTES) // 36864 (A, B)
#define NSTAGE 3
#define SMEM_GEMM (NSTAGE*STAGE_BYTES) // 110592 -> 2 CTA/SM

// ---------------- scratch (static device globals; no allocation) ----------------
__device__ float d_rnorm[VOCAB];
__device__ float d_x   [MTOT*DE];
__device__ __half d_qkvg[(size_t)MTOT*QS];
__device__ __half d_xh [MTOT*DE];
__device__ __half d_hhh[MTOT*DE];
__device__ __half d_eh [(size_t)VOCAB*DE];
__device__ __half d_wh [(size_t)5*NL*DE*DE];   // [l][Wq,Wk,Wv,Wg], then [l][Wo]
__device__ float4 d_tab[NL*NH*TABSTRIDE];      // (mask, cosD, sinD, 0) per (l,h,-rel)

__device__ __forceinline__ float wredsum(float x) {
#pragma unroll
    for (int o = 16; o > 0; o >>= 1) x += __shfl_xor_sync(0xFFFFFFFFu, x, o);
    return x;
}
__device__ __forceinline__ unsigned smem_u32(const void* p) {
    return (unsigned)__cvta_generic_to_shared(p);
}
__device__ __forceinline__ float ftanh(float x) {
    float y;
    asm("tanh.approx.f32 %0, %1;" : "=f"(y) : "f"(x));
    return y;
}

#define CP16(dst_u32, src_ptr) \
    asm volatile("cp.async.cg.shared.global [%0], [%1], 16;" :: "r"(dst_u32), "l"(src_ptr))
#define CP_COMMIT() asm volatile("cp.async.commit_group;" ::: "memory")
#define CP_WAIT(N)  asm volatile("cp.async.wait_group %0;" :: "n"(N) : "memory")

// ---------------- fused: embed row norm + fp16 conversion (MLP=4 per thread) ----------
__global__ void rnormconv_kernel(const float* __restrict__ embed, float* __restrict__ rnorm,
                                 __half* __restrict__ eh) {
    int v = blockIdx.x;
    int tid = threadIdx.x;                 // 64 threads
    const float4* row = (const float4*)(embed + (size_t)v * DE);   // 256 float4
    float4 f0 = row[tid];
    float4 f1 = row[tid + 64];
    float4 f2 = row[tid + 128];
    float4 f3 = row[tid + 192];
    float s = f0.x*f0.x + f0.y*f0.y + f0.z*f0.z + f0.w*f0.w
            + f1.x*f1.x + f1.y*f1.y + f1.z*f1.z + f1.w*f1.w
            + f2.x*f2.x + f2.y*f2.y + f2.z*f2.z + f2.w*f2.w
            + f3.x*f3.x + f3.y*f3.y + f3.z*f3.z + f3.w*f3.w;
    s = wredsum(s);
    __shared__ float sh2[2];
    if ((tid & 31) == 0) sh2[tid >> 5] = s;
    __syncthreads();
    if (tid == 0) rnorm[v] = 1.0f / fmaxf(sqrtf(sh2[0] + sh2[1]), 1e-12f);
    __half2* H = (__half2*)(eh + (size_t)v * DE);
    H[2*tid]           = __floats2half2_rn(f0.x, f0.y);
    H[2*tid+1]         = __floats2half2_rn(f0.z, f0.w);
    H[2*(tid+64)]      = __floats2half2_rn(f1.x, f1.y);
    H[2*(tid+64)+1]    = __floats2half2_rn(f1.z, f1.w);
    H[2*(tid+128)]     = __floats2half2_rn(f2.x, f2.y);
    H[2*(tid+128)+1]   = __floats2half2_rn(f2.z, f2.w);
    H[2*(tid+192)]     = __floats2half2_rn(f3.x, f3.y);
    H[2*(tid+192)+1]   = __floats2half2_rn(f3.z, f3.w);
}

// ---------------- embedding lookup: writes x fp32 and xh fp16 ----------------
__global__ void embed_kernel(const int* __restrict__ ids, const float* __restrict__ embed,
                             const float* __restrict__ rnorm, const float* __restrict__ sE,
                             float* __restrict__ x, __half* __restrict__ xh) {
    int m = blockIdx.x;
    int id = ids[m];
    float sc = rnorm[id] * expf(*sE);
    const float4* row = (const float4*)(embed + (size_t)id * DE);
    int i = threadIdx.x;
    float4 r = row[i];
    r.x *= sc; r.y *= sc; r.z *= sc; r.w *= sc;
    ((float4*)(x + (size_t)m * DE))[i] = r;
    __half2* hp = (__half2*)(xh + (size_t)m * DE);
    hp[2*i]   = __floats2half2_rn(r.x, r.y);
    hp[2*i+1] = __floats2half2_rn(r.z, r.w);
}

// ---------------- ALL weights fp32 -> fp16, one launch, 4 float4/thread ----------------
__global__ void convall_kernel(const float* __restrict__ Wq, const float* __restrict__ Wk,
                               const float* __restrict__ Wv, const float* __restrict__ Wg,
                               const float* __restrict__ Wo, __half* __restrict__ wh) {
    const size_t LW  = (size_t)DE * DE;
    const size_t QPM = LW / 4;
    size_t qbase = ((size_t)blockIdx.x * blockDim.x + threadIdx.x) * 4;
    float4 v[4];
    __half2* Hd[4];
    size_t offs[4];
#pragma unroll
    for (int u = 0; u < 4; u++) {
        size_t q = qbase + u;
        int mat = (int)(q / QPM);
        size_t off = q % QPM;
        const float* src;
        size_t dst;
        if (mat < 16) {
            int l = mat >> 2, f = mat & 3;
            src = (f == 0 ? Wq : f == 1 ? Wk : f == 2 ? Wv : Wg) + (size_t)l * LW;
            dst = (size_t)l * 4 * LW + (size_t)f * LW;
        } else {
            int l = mat - 16;
            src = Wo + (size_t)l * LW;
            dst = (size_t)NL * 4 * LW + (size_t)l * LW;
        }
        v[u] = ((const float4*)src)[off];
        Hd[u] = (__half2*)(wh + dst);
        offs[u] = off;
    }
#pragma unroll
    for (int u = 0; u < 4; u++) {
        Hd[u][2*offs[u]]   = __floats2half2_rn(v[u].x, v[u].y);
        Hd[u][2*offs[u]+1] = __floats2half2_rn(v[u].z, v[u].w);
    }
}

// ---------------- per-(l,h,rel) mask/rotation table (precise trig, one launch) --------
__global__ void tab_kernel(const float* __restrict__ sw_all, float4* __restrict__ tab) {
    int l = blockIdx.x >> 4;
    int h = blockIdx.x & 15;
    int j = threadIdx.x;                 // j = -rel
    if (j >= 129) return;
    float w = expf(sw_all[l*NH + h]) + 1.0f;
    float phi = (w < 128.0f) ? 0.5f * (cosf(PI_F * w / 128.0f) + 1.0f) : 0.0f;
    float phiw = phi / w;
    float rel = -(float)j;
    float mask = 0.5f * (cosf(PI_F * rel / w) + 1.0f);
    float D = rel * phiw;
    tab[(size_t)(l*NH + h) * TABSTRIDE + j] = make_float4(mask, cosf(D), sinf(D), 0.0f);
}

// ---------------- fp16 tensor-core NT GEMM, cp.async 3-stage, BK=64, K=1024 ----------
#define MMA_F16(C, A, B)                                                       \
    asm volatile(                                                              \
        "mma.sync.aligned.m16n8k16.row.col.f32.f16.f16.f32 "                   \
        "{%0,%1,%2,%3}, {%4,%5,%6,%7}, {%8,%9}, {%0,%1,%2,%3};\n"              \
        : "+f"((C)[0]), "+f"((C)[1]), "+f"((C)[2]), "+f"((C)[3])               \
        : "r"((A)[0]), "r"((A)[1]), "r"((A)[2]), "r"((A)[3]),                  \
          "r"((B)[0]), "r"((B)[1]))

__global__ __launch_bounds__(256, 2) void gemm_f16(
    const __half* __restrict__ A, const __half* __restrict__ B,
    float* __restrict__ C, int M, int N,
    const float* __restrict__ colScale, const float* __restrict__ scalarLog,
    int accumulate, __half* __restrict__ Chalf, int normKV)
{
    extern __shared__ __align__(128) char smem[];
    uint32_t sbase = smem_u32(smem);

    int tid  = threadIdx.x;
    int lane = tid & 31;
    int warp = tid >> 5;
    int wm = (warp >> 2) * 64;
    int wn = (warp & 3) * 32;
    int bm = blockIdx.y * BM;
    int bn = blockIdx.x * BN;

    int r0  = tid >> 3;            // 0..31
    int c16 = tid & 7;             // 0..7
    const char* gA0 = (const char*)(A + (size_t)(bm + r0) * GK + c16 * 8);
    const char* gB0 = (const char*)(B + (size_t)(bn + r0) * GK + c16 * 8);
    uint32_t s0 = r0 * (SPAD*2) + c16 * 16;
    const size_t rowstep = (size_t)32 * GK * 2;   // compile-time constant
    const uint32_t srowstep = 32 * (SPAD*2);

#define PREFETCH(st, k0)                                                       \
    {                                                                          \
        uint32_t sd = sbase + (st) * STAGE_BYTES;                              \
        size_t gk = (size_t)(k0) * 2;                                          \
        _Pragma("unroll")                                                      \
        for (int i = 0; i < 4; i++) {                                          \
            CP16(sd + 0*PLANE_BYTES + s0 + i*srowstep, gA0 + gk + i*rowstep);  \
            CP16(sd + 1*PLANE_BYTES + s0 + i*srowstep, gB0 + gk + i*rowstep);  \
        }                                                                      \
        CP_COMMIT();                                                           \
    }

    float c[4][4][4];
#pragma unroll
    for (int i = 0; i < 4; i++)
#pragma unroll
        for (int j = 0; j < 4; j++)
#pragma unroll
            for (int q = 0; q < 4; q++) c[i][j][q] = 0.f;

    int arow_l = lane & 15;
    int acol_l = (lane >> 4) << 3;
    int brow_l = (lane & 7) + ((lane >> 4) << 3);
    int bcol_l = ((lane >> 3) & 1) << 3;

    const int niter = GK / BK;          // 16, compile-time
    PREFETCH(0, 0);
    PREFETCH(1, BK);
    CP_WAIT(1);
    __syncthreads();

#pragma unroll 2
    for (int it = 0; it < niter; ++it) {
        int st = it % NSTAGE;
        if (it + 2 < niter) PREFETCH((it + 2) % NSTAGE, (it + 2) * BK);

        const __half* sA = (const __half*)(smem + st*STAGE_BYTES + 0*PLANE_BYTES);
        const __half* sB = (const __half*)(smem + st*STAGE_BYTES + 1*PLANE_BYTES);

#pragma unroll
        for (int ks = 0; ks < 4; ks++) {
            unsigned Af[4][4], Bf[4][2];
            int acol = ks * 16 + acol_l;
            int bcol = ks * 16 + bcol_l;
#pragma unroll
            for (int mt = 0; mt < 4; mt++) {
                unsigned sa = smem_u32(&sA[(wm + mt*16 + arow_l) * SPAD + acol]);
                asm volatile("ldmatrix.sync.aligned.m8n8.x4.shared.b16 {%0,%1,%2,%3}, [%4];\n"
                    : "=r"(Af[mt][0]), "=r"(Af[mt][1]), "=r"(Af[mt][2]), "=r"(Af[mt][3]) : "r"(sa));
            }
#pragma unroll
            for (int p = 0; p < 2; p++) {
                unsigned sb = smem_u32(&sB[(wn + p*16 + brow_l) * SPAD + bcol]);
                unsigned q0, q1, q2, q3;
                asm volatile("ldmatrix.sync.aligned.m8n8.x4.shared.b16 {%0,%1,%2,%3}, [%4];\n"
                    : "=r"(q0), "=r"(q1), "=r"(q2), "=r"(q3) : "r"(sb));
                Bf[p*2][0] = q0; Bf[p*2][1] = q1; Bf[p*2+1][0] = q2; Bf[p*2+1][1] = q3;
            }
#pragma unroll
            for (int mt = 0; mt < 4; mt++)
#pragma unroll
                for (int nt = 0; nt < 4; nt++)
                    MMA_F16(c[mt][nt], Af[mt], Bf[nt]);
        }

        if (it + 1 < niter) {
            if (it + 2 < niter) { CP_WAIT(1); } else { CP_WAIT(0); }
            __syncthreads();
        }
    }

    int g  = lane >> 2;
    int t2 = (lane & 3) * 2;

    // ---- fused k/v head normalization (fused qkvg GEMM only) ----
    if (normKV && ((bn >> 10) == 1 || (bn >> 10) == 2)) {
        float* ssum = (float*)smem;          // 128 rows x 4 col-groups
        __syncthreads();                     // mainloop smem reads done
#pragma unroll
        for (int mt = 0; mt < 4; mt++) {
#pragma unroll
            for (int rh = 0; rh < 2; rh++) {
                float p = 0.f;
#pragma unroll
                for (int nt = 0; nt < 4; nt++) {
                    float a = c[mt][nt][rh*2], b = c[mt][nt][rh*2+1];
                    p = fmaf(a, a, p); p = fmaf(b, b, p);
                }
                p += __shfl_xor_sync(0xFFFFFFFFu, p, 1);
                p += __shfl_xor_sync(0xFFFFFFFFu, p, 2);
                if ((lane & 3) == 0)
                    ssum[(wm + mt*16 + g + rh*8) * 4 + (wn >> 5)] = p;
            }
        }
        __syncthreads();
        int basegrp = (wn >> 5) & ~1;
#pragma unroll
        for (int mt = 0; mt < 4; mt++) {
#pragma unroll
            for (int rh = 0; rh < 2; rh++) {
                int rl = wm + mt*16 + g + rh*8;
                float hs = ssum[rl*4 + basegrp] + ssum[rl*4 + basegrp + 1];
                float ik = 1.0f / fmaxf(sqrtf(hs), 1e-12f);
#pragma unroll
                for (int nt = 0; nt < 4; nt++) {
                    c[mt][nt][rh*2]   *= ik;
                    c[mt][nt][rh*2+1] *= ik;
                }
            }
        }
    }

    // epilogue
    float sc = scalarLog ? __expf(*scalarLog) : 1.0f;
#pragma unroll
    for (int mt = 0; mt < 4; mt++) {
#pragma unroll
        for (int nt = 0; nt < 4; nt++) {
            int row = bm + wm + mt*16 + g;
            int col = bn + wn + nt*8 + t2;
            float cs0 = colScale ? colScale[col]   : 1.0f;
            float cs1 = colScale ? colScale[col+1] : 1.0f;
            float v0 = c[mt][nt][0] * sc * cs0;
            float v1 = c[mt][nt][1] * sc * cs1;
            float v2 = c[mt][nt][2] * sc * cs0;
            float v3 = c[mt][nt][3] * sc * cs1;
            if (C) {
                float* p0 = C + (size_t)row * N + col;
                float* p1 = C + (size_t)(row + 8) * N + col;
                if (accumulate) {
                    v0 += p0[0]; v1 += p0[1];
                    v2 += p1[0]; v3 += p1[1];
                }
                float2 a; a.x = v0; a.y = v1; *(float2*)p0 = a;
                float2 b; b.x = v2; b.y = v3; *(float2*)p1 = b;
            }
            if (Chalf) {
                *(__half2*)(Chalf + (size_t)row * N + col)       = __floats2half2_rn(v0, v1);
                *(__half2*)(Chalf + (size_t)(row + 8) * N + col) = __floats2half2_rn(v2, v3);
            }
        }
    }
}

// ---------------- fused attention: 8 lanes per (m,h), 4 units/warp ----------------
__global__ void attn_kernel(const __half* __restrict__ qkvg,
                            const float4* __restrict__ tabl,
                            const float* __restrict__ sw, const float* __restrict__ sr,
                            const float* __restrict__ sO, __half* __restrict__ hhh) {
    int gwarp = (blockIdx.x * blockDim.x + threadIdx.x) >> 5;
    int lane = threadIdx.x & 31;
    int u = lane >> 3;                 // unit 0..3
    int e = lane & 7;                  // element block 0..7
    int gid = gwarp * 4 + u;           // (h, m) unit id
    int h = gid >> 12;
    int m = gid & (MTOT - 1);
    int t = m & (SEQ - 1);

    float w  = __expf(sw[h]) + 1.0f;
    float r  = __expf(sr[h]) + 1.0f;
    float es = __expf(sO[h]);
    const float4* th = tabl + h * TABSTRIDE;

    size_t qoff = (size_t)m * QS + h * DK + e * 8;
    uint4 qraw = *(const uint4*)(qkvg + qoff);
    float qv[8];
    {
        const __half2* qh = (const __half2*)&qraw;
#pragma unroll
        for (int k2 = 0; k2 < 4; k2++) {
            float2 f = __half22float2(qh[k2]);
            qv[2*k2] = f.x; qv[2*k2+1] = f.y;
        }
    }
    float sq = 0.f;
#pragma unroll
    for (int k2 = 0; k2 < 8; k2++) sq = fmaf(qv[k2], qv[k2], sq);
    sq += __shfl_xor_sync(0xFFFFFFFFu, sq, 1);
    sq += __shfl_xor_sync(0xFFFFFFFFu, sq, 2);
    sq += __shfl_xor_sync(0xFFFFFFFFu, sq, 4);
    float iq = 1.0f / fmaxf(sqrtf(sq), 1e-12f);
#pragma unroll
    for (int k2 = 0; k2 < 8; k2++) qv[k2] *= iq;

    int LB = (int)ceilf(w) - 1;
    int lb = (LB > t) ? t : LB;        // per-unit lookback
    int tb0 = t - u;                   // t of unit 0 (warp-uniform)
    int lbmin = (LB > tb0) ? tb0 : LB; // warp-uniform common lookback

    const __half* kbase = qkvg + (size_t)(m - lb) * QS + h * DK + e * 8 + DE;

    float acc[8];
#pragma unroll
    for (int k2 = 0; k2 < 8; k2++) acc[k2] = 0.f;

#pragma unroll 4
    for (int i = 0; i <= lbmin; ++i) {
        const __half* kp = kbase + (size_t)i * QS;
        uint4 kraw = *(const uint4*)kp;
        uint4 vraw = *(const uint4*)(kp + DE);
        float4 tb = th[lb - i];
        float kf[8];
        {
            const __half2* kh = (const __half2*)&kraw;
#pragma unroll
            for (int k2 = 0; k2 < 4; k2++) {
                float2 f = __half22float2(kh[k2]);
                kf[2*k2] = f.x; kf[2*k2+1] = f.y;
            }
        }
        float d = 0.f;
#pragma unroll
        for (int k2 = 0; k2 < 8; k2++) d = fmaf(qv[k2], kf[k2], d);
        if (e == 0) {
            float pr = fmaf(qv[0], kf[0], qv[1] * kf[1]);
            float cr = qv[0] * kf[1] - qv[1] * kf[0];
            d = fmaf(tb.y - 1.0f, pr, fmaf(tb.z, cr, d));
        }
        d += __shfl_xor_sync(0xFFFFFFFFu, d, 1);
        d += __shfl_xor_sync(0xFFFFFFFFu, d, 2);
        d += __shfl_xor_sync(0xFFFFFFFFu, d, 4);
        float tmp = fmaxf(fmaf(r, d - 1.0f, 1.0f), 0.0f);
        float rho = tmp * tmp * tb.x;
        const __half2* vh = (const __half2*)&vraw;
#pragma unroll
        for (int k2 = 0; k2 < 4; k2++) {
            float2 f = __half22float2(vh[k2]);
            acc[2*k2]   = fmaf(rho, f.x, acc[2*k2]);
            acc[2*k2+1] = fmaf(rho, f.y, acc[2*k2+1]);
        }
    }

    if (lbmin < LB) {
#pragma unroll
        for (int ex = 1; ex <= 3; ++ex) {
            int i = lbmin + ex;
            bool valid = (i <= lb);
            int io = valid ? i : 0;
            const __half* kp = kbase + (size_t)io * QS;
            uint4 kraw = *(const uint4*)kp;
            uint4 vraw = *(const uint4*)(kp + DE);
            float4 tb = th[valid ? (lb - i) : 0];
            float mk = valid ? tb.x : 0.0f;
            float kf[8];
            {
                const __half2* kh = (const __half2*)&kraw;
#pragma unroll
                for (int k2 = 0; k2 < 4; k2++) {
                    float2 f = __half22float2(kh[k2]);
                    kf[2*k2] = f.x; kf[2*k2+1] = f.y;
                }
            }
            float d = 0.f;
#pragma unroll
            for (int k2 = 0; k2 < 8; k2++) d = fmaf(qv[k2], kf[k2], d);
            if (e == 0) {
                float pr = fmaf(qv[0], kf[0], qv[1] * kf[1]);
                float cr = qv[0] * kf[1] - qv[1] * kf[0];
                d = fmaf(tb.y - 1.0f, pr, fmaf(tb.z, cr, d));
            }
            d += __shfl_xor_sync(0xFFFFFFFFu, d, 1);
            d += __shfl_xor_sync(0xFFFFFFFFu, d, 2);
            d += __shfl_xor_sync(0xFFFFFFFFu, d, 4);
            float tmp = fmaxf(fmaf(r, d - 1.0f, 1.0f), 0.0f);
            float rho = tmp * tmp * mk;
            const __half2* vh = (const __half2*)&vraw;
#pragma unroll
            for (int k2 = 0; k2 < 4; k2++) {
                float2 f = __half22float2(vh[k2]);
                acc[2*k2]   = fmaf(rho, f.x, acc[2*k2]);
                acc[2*k2+1] = fmaf(rho, f.y, acc[2*k2+1]);
            }
        }
    }

    float hn2 = 0.f;
#pragma unroll
    for (int k2 = 0; k2 < 8; k2++) hn2 = fmaf(acc[k2], acc[k2], hn2);
    hn2 += __shfl_xor_sync(0xFFFFFFFFu, hn2, 1);
    hn2 += __shfl_xor_sync(0xFFFFFFFFu, hn2, 2);
    hn2 += __shfl_xor_sync(0xFFFFFFFFu, hn2, 4);
    float hn = fmaxf(sqrtf(hn2), 1e-8f);
    float us = ftanh(hn) / hn;

    uint4 graw = *(const uint4*)(qkvg + qoff + 3*DE);
    uint4 oraw;
    __half2* oh = (__half2*)&oraw;
    const __half2* gh = (const __half2*)&graw;
#pragma unroll
    for (int k2 = 0; k2 < 4; k2++) {
        float2 gf = __half22float2(gh[k2]);
        float s0 = gf.x / (1.0f + __expf(-gf.x));
        float s1 = gf.y / (1.0f + __expf(-gf.y));
        float g0 = ftanh(s0), g1 = ftanh(s1);
        float o0 = acc[2*k2]   * us * g0 * es;
        float o1 = acc[2*k2+1] * us * g1 * es;
        oh[k2] = __floats2half2_rn(o0, o1);
    }
    *(uint4*)(hhh + (size_t)m * DE + h * DK + e * 8) = oraw;
}

// ---------------- launch ----------------
extern "C" void kernel_launch(void* const* d_in, const int* in_sizes, int n_in,
                              void* d_out, int out_size) {
    const int*   ids   = (const int*)d_in[0];
    const float* embed = (const float*)d_in[1];
    const float* sE    = (const float*)d_in[2];
    const float* sF    = (const float*)d_in[3];
    const float* Wq    = (const float*)d_in[4];
    const float* Wk    = (const float*)d_in[5];
    const float* Wv    = (const float*)d_in[6];
    const float* Wg    = (const float*)d_in[7];
    const float* Wo    = (const float*)d_in[8];
    const float* sw    = (const float*)d_in[9];
    const float* sr    = (const float*)d_in[10];
    const float* sO    = (const float*)d_in[11];
    float* out = (float*)d_out;

    cudaFuncSetAttribute(gemm_f16, cudaFuncAttributeMaxDynamicSharedMemorySize, SMEM_GEMM);

    float *x, *rn;
    cudaGetSymbolAddress((void**)&x,   d_x);
    cudaGetSymbolAddress((void**)&rn,  d_rnorm);
    float4* tab;
    cudaGetSymbolAddress((void**)&tab, d_tab);
    __half *qkvg, *xh, *hhh, *eh, *wh;
    cudaGetSymbolAddress((void**)&qkvg, d_qkvg);
    cudaGetSymbolAddress((void**)&xh,  d_xh);
    cudaGetSymbolAddress((void**)&hhh, d_hhh);
    cudaGetSymbolAddress((void**)&eh,  d_eh);
    cudaGetSymbolAddress((void**)&wh,  d_wh);

    const size_t LW = (size_t)DE * DE;
    const size_t WO_BASE = (size_t)NL * 4 * LW;

    rnormconv_kernel<<<VOCAB, 64>>>(embed, rn, eh);
    embed_kernel<<<MTOT, 256>>>(ids, embed, rn, sE, x, xh);
    convall_kernel<<<(int)(20 * LW / 4 / 1024), 256>>>(Wq, Wk, Wv, Wg, Wo, wh);
    tab_kernel<<<NL*NH, 160>>>(sw, tab);

    dim3 gfused(QS / BN, MTOT / BM);   // (32, 32)
    dim3 gwo(DE / BN, MTOT / BM);      // (8, 32)
    int units = MTOT * NH;             // 65536
    int nblk_attn = (units / 4 * 32) / 256;   // 2048 blocks

    for (int l = 0; l < NL; ++l) {
        size_t fb = (size_t)l * 4 * LW;
        const float* swl = sw + l * NH;
        const float* srl = sr + l * NH;
        const float* sOl = sO + l * NH;
        const float4* tabl = tab + (size_t)l * NH * TABSTRIDE;

        gemm_f16<<<gfused, 256, SMEM_GEMM>>>(xh, wh + fb, nullptr,
                                             MTOT, QS, nullptr, nullptr, 0, qkvg, 1);
        attn_kernel<<<nblk_attn, 256>>>(qkvg, tabl, swl, srl, sOl, hhh);
        gemm_f16<<<gwo, 256, SMEM_GEMM>>>(hhh, wh + WO_BASE + l*LW, x,
                                          MTOT, DE, nullptr, nullptr, 1, xh, 0);
    }

    dim3 gfin(VOCAB / BN, MTOT / BM);  // (250, 32)
    gemm_f16<<<gfin, 256, SMEM_GEMM>>>(xh, eh, out, MTOT, VOCAB, rn, sF, 0, nullptr, 0);
}